// round 1
// baseline (speedup 1.0000x reference)
#include <cuda_runtime.h>

// TemperatureScaler: piecewise-linear temperature scaling of logits.
// out = T[bin]*(x - thr_pad[bin]) + c_pad[bin], bin = searchsorted(sorted_thr, x, 'left')

#define TS_TEMP_MIN 1e-4f

__global__ __launch_bounds__(256) void ts_kernel(
    const float4* __restrict__ in, float4* __restrict__ out,
    const float* __restrict__ temperature, const float* __restrict__ thresholds,
    int n4)
{
    __shared__ float4 lut[8];   // (T, thr_pad, c_pad, 0)
    __shared__ float sthr[8];   // sorted thresholds for bin search

    if (threadIdx.x == 0) {
        float th[7];
        #pragma unroll
        for (int i = 0; i < 7; i++) th[i] = thresholds[i];
        // insertion sort (7 elements) == jnp.sort
        #pragma unroll
        for (int i = 1; i < 7; i++) {
            float v = th[i];
            int j = i - 1;
            while (j >= 0 && th[j] > v) { th[j + 1] = th[j]; j--; }
            th[j + 1] = v;
        }
        float T[8];
        #pragma unroll
        for (int i = 0; i < 8; i++) {
            float t = temperature[i];
            T[i] = t < TS_TEMP_MIN ? TS_TEMP_MIN : t;   // clip(lo=1e-4)
        }
        float thrp[8];
        thrp[0] = 0.0f;
        #pragma unroll
        for (int i = 0; i < 7; i++) thrp[i + 1] = th[i];
        // c = cumsum(diff(pad(thr, left0)) * T[:-1]) — same op ordering as reference
        float c[8];
        c[0] = 0.0f;
        #pragma unroll
        for (int i = 0; i < 7; i++) {
            float d = __fadd_rn(thrp[i + 1], -thrp[i]);
            c[i + 1] = __fadd_rn(c[i], __fmul_rn(d, T[i]));
        }
        #pragma unroll
        for (int i = 0; i < 8; i++) lut[i] = make_float4(T[i], thrp[i], c[i], 0.0f);
        #pragma unroll
        for (int i = 0; i < 7; i++) sthr[i] = th[i];
    }
    __syncthreads();

    // broadcast thresholds into registers (conflict-free LDS broadcast)
    const float t0 = sthr[0], t1 = sthr[1], t2 = sthr[2], t3 = sthr[3],
                t4 = sthr[4], t5 = sthr[5], t6 = sthr[6];

    auto piece = [&](float x) -> float {
        // searchsorted(thr, x, side='left') == count of thr_j < x (equality -> lower bin)
        int b = 0;
        b += (x > t0); b += (x > t1); b += (x > t2); b += (x > t3);
        b += (x > t4); b += (x > t5); b += (x > t6);
        float4 L = lut[b];
        // T[b]*(x - thrp[b]) + c[b], no FMA contraction (match reference rounding)
        return __fadd_rn(__fmul_rn(L.x, __fadd_rn(x, -L.y)), L.z);
    };

    int i = blockIdx.x * blockDim.x + threadIdx.x;
    const int stride = gridDim.x * blockDim.x;

    // 2-way batched main loop: two independent LDG.128 in flight per thread
    for (; i + stride < n4; i += 2 * stride) {
        float4 a  = in[i];
        float4 b4 = in[i + stride];
        float4 ra, rb;
        ra.x = piece(a.x);  ra.y = piece(a.y);  ra.z = piece(a.z);  ra.w = piece(a.w);
        rb.x = piece(b4.x); rb.y = piece(b4.y); rb.z = piece(b4.z); rb.w = piece(b4.w);
        out[i] = ra;
        out[i + stride] = rb;
    }
    for (; i < n4; i += stride) {
        float4 a = in[i];
        float4 r;
        r.x = piece(a.x); r.y = piece(a.y); r.z = piece(a.z); r.w = piece(a.w);
        out[i] = r;
    }
}

// Scalar tail for out_size % 4 != 0 (not hit for B=64, V=128000; kept for generality)
__global__ void ts_tail_kernel(
    const float* __restrict__ in, float* __restrict__ out,
    const float* __restrict__ temperature, const float* __restrict__ thresholds,
    int start, int n)
{
    float th[7];
    #pragma unroll
    for (int i = 0; i < 7; i++) th[i] = thresholds[i];
    #pragma unroll
    for (int i = 1; i < 7; i++) {
        float v = th[i];
        int j = i - 1;
        while (j >= 0 && th[j] > v) { th[j + 1] = th[j]; j--; }
        th[j + 1] = v;
    }
    float T[8];
    #pragma unroll
    for (int i = 0; i < 8; i++) {
        float t = temperature[i];
        T[i] = t < TS_TEMP_MIN ? TS_TEMP_MIN : t;
    }
    float thrp[8];
    thrp[0] = 0.0f;
    #pragma unroll
    for (int i = 0; i < 7; i++) thrp[i + 1] = th[i];
    float c[8];
    c[0] = 0.0f;
    #pragma unroll
    for (int i = 0; i < 7; i++) {
        float d = __fadd_rn(thrp[i + 1], -thrp[i]);
        c[i + 1] = __fadd_rn(c[i], __fmul_rn(d, T[i]));
    }
    for (int i = start + threadIdx.x; i < n; i += blockDim.x) {
        float x = in[i];
        int b = 0;
        #pragma unroll
        for (int j = 0; j < 7; j++) b += (x > th[j]);
        out[i] = __fadd_rn(__fmul_rn(T[b], __fadd_rn(x, -thrp[b])), c[b]);
    }
}

extern "C" void kernel_launch(void* const* d_in, const int* in_sizes, int n_in,
                              void* d_out, int out_size) {
    const float* logits      = (const float*)d_in[0];
    const float* temperature = (const float*)d_in[1];
    const float* thresholds  = (const float*)d_in[2];
    float* out = (float*)d_out;

    int n  = out_size;           // 8,192,000
    int n4 = n >> 2;             // 2,048,000 float4s
    const int threads = 256;
    int grid = (n4 + threads * 2 - 1) / (threads * 2);   // 2 float4 per thread -> 4000 blocks
    if (grid < 1) grid = 1;

    ts_kernel<<<grid, threads>>>((const float4*)logits, (float4*)out,
                                 temperature, thresholds, n4);

    int rem = n - (n4 << 2);
    if (rem > 0) {
        ts_tail_kernel<<<1, 256>>>(logits, out, temperature, thresholds, n4 << 2, n);
    }
}

// round 3
// speedup vs baseline: 1.1604x; 1.1604x over previous
#include <cuda_runtime.h>

// TemperatureScaler: piecewise-linear temperature scaling of logits.
// out = T[b]*x + C[b],  b = searchsorted(sorted_thr, x, 'left'),
// C[b] = c[b] - T[b]*thr_pad[b]  (single-FFMA refactoring of the continuous
// piecewise-linear map; introduces only ulp-level error).

#define TS_TEMP_MIN 1e-4f

__device__ __forceinline__ void ts_build_params(
    const float* __restrict__ temperature, const float* __restrict__ thresholds,
    float* th /*7 sorted*/, float* T /*8*/, float* C /*8*/)
{
    #pragma unroll
    for (int i = 0; i < 7; i++) th[i] = thresholds[i];
    // insertion sort (7 elements) == jnp.sort
    #pragma unroll
    for (int i = 1; i < 7; i++) {
        float v = th[i];
        int j = i - 1;
        while (j >= 0 && th[j] > v) { th[j + 1] = th[j]; j--; }
        th[j + 1] = v;
    }
    #pragma unroll
    for (int i = 0; i < 8; i++) {
        float t = temperature[i];
        T[i] = t < TS_TEMP_MIN ? TS_TEMP_MIN : t;   // clip(lo=1e-4)
    }
    float thrp[8];
    thrp[0] = 0.0f;
    #pragma unroll
    for (int i = 0; i < 7; i++) thrp[i + 1] = th[i];
    // c = cumsum(diff(pad(thr, left0)) * T[:-1])
    float c[8];
    c[0] = 0.0f;
    #pragma unroll
    for (int i = 0; i < 7; i++) {
        float d = __fadd_rn(thrp[i + 1], -thrp[i]);
        c[i + 1] = __fadd_rn(c[i], __fmul_rn(d, T[i]));
    }
    // C[b] = c[b] - T[b]*thrp[b]  (fused for accuracy)
    #pragma unroll
    for (int i = 0; i < 8; i++) C[i] = __fmaf_rn(-T[i], thrp[i], c[i]);
}

__global__ __launch_bounds__(256) void ts_kernel(
    const float4* __restrict__ in, float4* __restrict__ out,
    const float* __restrict__ temperature, const float* __restrict__ thresholds,
    int n4)
{
    __shared__ float2 lut[8];   // (T, C)
    __shared__ float sthr[7];   // sorted thresholds

    if (threadIdx.x == 0) {
        float th[7], T[8], C[8];
        ts_build_params(temperature, thresholds, th, T, C);
        #pragma unroll
        for (int i = 0; i < 8; i++) lut[i] = make_float2(T[i], C[i]);
        #pragma unroll
        for (int i = 0; i < 7; i++) sthr[i] = th[i];
    }
    __syncthreads();

    const float t0 = sthr[0], t1 = sthr[1], t2 = sthr[2], t3 = sthr[3],
                t4 = sthr[4], t5 = sthr[5], t6 = sthr[6];

    auto piece = [&](float x) -> float {
        // count of thr_j < x  (side='left': equality -> lower bin)
        int b = (x > t0);
        b += (x > t1); b += (x > t2); b += (x > t3);
        b += (x > t4); b += (x > t5); b += (x > t6);
        float2 L = lut[b];                     // LDS.64, conflict-free
        return __fmaf_rn(L.x, x, L.y);         // one FFMA
    };

    const int base = blockIdx.x * 1024 + threadIdx.x;

    if (base + 768 < n4) {
        // fast path: 4 independent LDG.128 in flight (MLP=4)
        float4 v0 = in[base];
        float4 v1 = in[base + 256];
        float4 v2 = in[base + 512];
        float4 v3 = in[base + 768];
        float4 r0, r1, r2, r3;
        r0.x = piece(v0.x); r0.y = piece(v0.y); r0.z = piece(v0.z); r0.w = piece(v0.w);
        r1.x = piece(v1.x); r1.y = piece(v1.y); r1.z = piece(v1.z); r1.w = piece(v1.w);
        r2.x = piece(v2.x); r2.y = piece(v2.y); r2.z = piece(v2.z); r2.w = piece(v2.w);
        r3.x = piece(v3.x); r3.y = piece(v3.y); r3.z = piece(v3.z); r3.w = piece(v3.w);
        out[base]       = r0;
        out[base + 256] = r1;
        out[base + 512] = r2;
        out[base + 768] = r3;
    } else {
        #pragma unroll
        for (int k = 0; k < 4; k++) {
            int i = base + k * 256;
            if (i < n4) {
                float4 v = in[i];
                float4 r;
                r.x = piece(v.x); r.y = piece(v.y); r.z = piece(v.z); r.w = piece(v.w);
                out[i] = r;
            }
        }
    }
}

// Scalar tail for out_size % 4 != 0 (not hit for B=64, V=128000)
__global__ void ts_tail_kernel(
    const float* __restrict__ in, float* __restrict__ out,
    const float* __restrict__ temperature, const float* __restrict__ thresholds,
    int start, int n)
{
    float th[7], T[8], C[8];
    ts_build_params(temperature, thresholds, th, T, C);
    for (int i = start + threadIdx.x; i < n; i += blockDim.x) {
        float x = in[i];
        int b = 0;
        #pragma unroll
        for (int j = 0; j < 7; j++) b += (x > th[j]);
        out[i] = __fmaf_rn(T[b], x, C[b]);
    }
}

extern "C" void kernel_launch(void* const* d_in, const int* in_sizes, int n_in,
                              void* d_out, int out_size) {
    const float* logits      = (const float*)d_in[0];
    const float* temperature = (const float*)d_in[1];
    const float* thresholds  = (const float*)d_in[2];
    float* out = (float*)d_out;

    int n  = out_size;           // 8,192,000
    int n4 = n >> 2;             // 2,048,000 float4s

    int grid = (n4 + 1023) / 1024;   // 4 float4 per thread -> 2000 blocks
    if (grid < 1) grid = 1;

    ts_kernel<<<grid, 256>>>((const float4*)logits, (float4*)out,
                             temperature, thresholds, n4);

    int rem = n - (n4 << 2);
    if (rem > 0) {
        ts_tail_kernel<<<1, 256>>>(logits, out, temperature, thresholds, n4 << 2, n);
    }
}